// round 1
// baseline (speedup 1.0000x reference)
#include <cuda_runtime.h>

#define T_STEPS 730
#define N_GRID  8000
#define NZ      1e-5f

__constant__ float c_LO[18] = {-3.f, 0.f, 0.f, 0.f, 0.f, 0.f, 0.f, 0.f, 0.005f, 1.f, 0.f, 1.f, 0.f, 1.f, 0.f, 0.f, 0.f, 0.f};
__constant__ float c_HI[18] = { 5.f,20.f, 1.f, 1.f, 5.f,50.f, 1.f, 1.f, 0.995f, 2000.f, 20.f, 300.f, 1.f, 5.f, 1.f, 1.f, 1.f, 1.f};

__global__ __launch_bounds__(64) void prms_kernel(
    const float* __restrict__ x,      // [T_STEPS, N_GRID, 3]
    const float* __restrict__ params, // [T_STEPS, N_GRID, 18]
    float* __restrict__ out)          // [T_STEPS, N_GRID]
{
    const int g = blockIdx.x * blockDim.x + threadIdx.x;
    if (g >= N_GRID) return;

    // ---- per-cell parameters from the LAST timestep slice ----
    const float* pp = params + ((size_t)(T_STEPS - 1) * N_GRID + g) * 18;
    float pr[18];
#pragma unroll
    for (int i = 0; i < 18; i++) {
        float s = 1.0f / (1.0f + expf(-pp[i]));          // sigmoid (accurate)
        pr[i] = c_LO[i] + s * (c_HI[i] - c_LO[i]);
    }
    const float tt     = pr[0],  ddf   = pr[1],  alpha = pr[2],  beta  = pr[3];
    const float stor   = pr[4],  retip = pr[5],  fscn  = pr[6],  scx   = pr[7];
    const float flz    = pr[8],  stot  = pr[9],  cgw   = pr[10], resmax= pr[11];
    const float k1     = pr[12], k2    = pr[13], k3    = pr[14], k4    = pr[15];
    const float k5     = pr[16], k6    = pr[17];

    const float scn        = fscn * scx;
    const float remx       = (1.0f - flz) * stot;
    const float smax       = flz * stot;
    const float inv_remx   = 1.0f / remx;
    const float inv_smax   = 1.0f / smax;
    const float inv_resmax = 1.0f / resmax;
    const float one_m_beta = 1.0f - beta;
    const float one_m_alpha= 1.0f - alpha;
    const float scx_m_scn  = scx - scn;

    // ---- state ----
    float snow = 0.001f, xin = 0.001f, rstor = 0.001f, rechr = 0.001f;
    float smav = 0.001f, res = 0.001f, gw = 0.001f;

    // ---- depth-2 register prefetch pipeline for x ----
    float Pb[2], Tb[2], Eb[2];
    {
        const float* x0 = x + (size_t)g * 3;                      // t = 0
        Pb[0] = x0[0]; Tb[0] = x0[1]; Eb[0] = x0[2];
        const float* x1 = x + ((size_t)N_GRID + g) * 3;           // t = 1
        Pb[1] = x1[0]; Tb[1] = x1[1]; Eb[1] = x1[2];
    }

#pragma unroll 2
    for (int t = 0; t < T_STEPS; t++) {
        const int b = t & 1;
        const float P  = Pb[b];
        const float Tc = Tb[b];
        const float Ep = Eb[b];

        // issue prefetch for t+2 immediately (2 iterations of compute to hide it)
        const int tn = t + 2;
        if (tn < T_STEPS) {
            const float* xn = x + ((size_t)tn * N_GRID + g) * 3;
            Pb[b] = xn[0]; Tb[b] = xn[1]; Eb[b] = xn[2];
        }

        // ---- snow ----
        const float is_snow  = (Tc <= tt) ? 1.0f : 0.0f;
        const float flux_ps  = P * is_snow;
        const float flux_pr  = P - flux_ps;                // == P*(1-is_snow), exact
        snow += flux_ps;
        float flux_m = fmaxf(ddf * (Tc - tt), 0.0f);
        flux_m = fminf(flux_m, snow);
        snow = fmaxf(snow - flux_m, NZ);

        // ---- interception ----
        const float flux_pim = flux_pr * one_m_beta;
        const float flux_psm = flux_pr * beta;
        const float flux_pby = flux_psm * one_m_alpha;
        const float flux_pin = flux_psm * alpha;
        xin += flux_pin;
        const float flux_ptf = fmaxf(xin - stor, 0.0f);
        xin = fmaxf(xin - flux_ptf, NZ);
        const float flux_ein = fminf(Ep * beta, xin);
        xin = fmaxf(xin - flux_ein, NZ);

        // ---- impervious storage ----
        const float flux_mim = flux_m * one_m_beta;
        const float flux_msm = flux_m * beta;
        rstor += flux_mim + flux_pim;
        const float flux_sas = fmaxf(rstor - retip, 0.0f);
        rstor = fmaxf(rstor - flux_sas, NZ);
        const float flux_eim = fminf(one_m_beta * Ep, rstor);
        rstor = fmaxf(rstor - flux_eim, NZ);

        // ---- surface runoff / recharge ----
        const float sro_lin = fminf(fmaxf(fmaf(scx_m_scn, rechr * inv_remx, scn), 0.0f), 1.0f);
        const float inflow  = flux_msm + flux_ptf + flux_pby;
        const float flux_sro = sro_lin * inflow;
        const float flux_inf = inflow - flux_sro;
        rechr += flux_inf;
        const float flux_pc = fmaxf(rechr - remx, 0.0f);
        rechr -= flux_pc;
        const float ep_net = Ep - flux_ein - flux_eim;
        const float evap_max_a = fmaxf(rechr * inv_remx * ep_net, 0.0f);
        const float flux_ea = fminf(evap_max_a, rechr);
        rechr = fmaxf(rechr - flux_ea, NZ);

        // ---- soil moisture ----
        smav += flux_pc;
        const float flux_excs = fmaxf(smav - smax, 0.0f);
        smav -= flux_excs;
        float transp = (rechr < ep_net)
                         ? fmaxf(smav * inv_smax * (ep_net - flux_ea), 0.0f)
                         : 0.0f;
        transp = fminf(transp, smav);
        smav = fmaxf(smav - transp, NZ);

        // ---- reservoir ----
        const float flux_sep  = fminf(cgw, flux_excs);
        const float flux_qres = fmaxf(flux_excs - flux_sep, 0.0f);
        res += flux_qres;
        float flux_gad = k1 * powf(res * inv_resmax, k2);
        flux_gad = fminf(flux_gad, res);
        res = fmaxf(res - flux_gad, NZ);
        float flux_ras = fminf(fmaf(k4 * res, res, k3 * res), res);
        res = fmaxf(res - flux_ras, NZ);

        // ---- groundwater ----
        gw += flux_gad + flux_sep;
        const float flux_bas = k5 * gw;
        gw = fmaxf(gw - flux_bas, NZ);
        const float flux_snk = k6 * gw;
        gw = fmaxf(gw - flux_snk, NZ);

        // ---- streamflow ----
        const float q = flux_sas + flux_sro + flux_bas + flux_ras;
        out[(size_t)t * N_GRID + g] = q;
    }
}

extern "C" void kernel_launch(void* const* d_in, const int* in_sizes, int n_in,
                              void* d_out, int out_size) {
    // Identify inputs by element count (robust to ordering):
    //   x:          730*8000*3  = 17,520,000
    //   parameters: 730*8000*18 = 105,120,000
    const float* x = nullptr;
    const float* params = nullptr;
    for (int i = 0; i < n_in; i++) {
        if (in_sizes[i] == T_STEPS * N_GRID * 3)  x = (const float*)d_in[i];
        if (in_sizes[i] == T_STEPS * N_GRID * 18) params = (const float*)d_in[i];
    }
    float* out = (float*)d_out;

    const int threads = 64;
    const int blocks = (N_GRID + threads - 1) / threads;  // 125 blocks
    prms_kernel<<<blocks, threads>>>(x, params, out);
}